// round 1
// baseline (speedup 1.0000x reference)
#include <cuda_runtime.h>
#include <cuda_bf16.h>

#define NB 16
#define NT 512
#define ND 384

// Per-batch inclusive cumsum scratch (no allocations allowed).
__device__ int g_cum[NB * NT];

// One block per batch row: inclusive scan of 512 durations (Hillis-Steele in smem).
// Also writes mel_lens (as float) into the output tail when present.
__global__ void cumsum_kernel(const int* __restrict__ dur, float* __restrict__ out_tail,
                              int has_tail) {
    __shared__ int s[NT];
    const int b = blockIdx.x;
    const int t = threadIdx.x;
    s[t] = dur[b * NT + t];
    __syncthreads();
    #pragma unroll
    for (int off = 1; off < NT; off <<= 1) {
        int v = (t >= off) ? s[t - off] : 0;
        __syncthreads();
        s[t] += v;
        __syncthreads();
    }
    g_cum[b * NT + t] = s[t];
    if (has_tail && t == NT - 1) out_tail[b] = (float)s[t];
}

// One warp per output row (b, pos). Each lane moves 3 float4 (96 float4 = 384 floats).
// Binary search (searchsorted right) over the L1/L2-resident cumsum; uniform per warp.
__global__ void expand_kernel(const float* __restrict__ enc, float* __restrict__ out,
                              int max_len) {
    const int gwarp = (blockIdx.x * blockDim.x + threadIdx.x) >> 5;
    const int lane  = threadIdx.x & 31;
    const int total_rows = NB * max_len;
    if (gwarp >= total_rows) return;

    const int b   = gwarp / max_len;
    const int pos = gwarp - b * max_len;

    const int* __restrict__ cum = g_cum + b * NT;
    const int mel = cum[NT - 1];

    float4* dst = (float4*)(out + (size_t)gwarp * ND);

    // valid <=> pos < min(mel, max_len); pos < max_len always holds here.
    if (pos >= mel) {
        const float4 z = make_float4(0.f, 0.f, 0.f, 0.f);
        #pragma unroll
        for (int j = 0; j < 3; j++) dst[lane + 32 * j] = z;
        return;
    }

    // first idx with cum[idx] > pos  (searchsorted side='right')
    int lo = 0, hi = NT;
    while (lo < hi) {
        int mid = (lo + hi) >> 1;
        if (cum[mid] <= pos) lo = mid + 1; else hi = mid;
    }
    const int tok = min(lo, NT - 1);

    const float4* src = (const float4*)(enc + ((size_t)b * NT + tok) * ND);
    #pragma unroll
    for (int j = 0; j < 3; j++) dst[lane + 32 * j] = src[lane + 32 * j];
}

// Zero-fill any residual tail elements beyond the mel_lens slot (defensive).
__global__ void fill_zero_kernel(float* __restrict__ p, long long n) {
    long long i = (long long)blockIdx.x * blockDim.x + threadIdx.x;
    if (i < n) p[i] = 0.f;
}

extern "C" void kernel_launch(void* const* d_in, const int* in_sizes, int n_in,
                              void* d_out, int out_size) {
    const float* enc = (const float*)d_in[0];
    const int*   dur = (const int*)d_in[1];
    float* out = (float*)d_out;

    // Derive max_len from out_size: out = [B, max_len, D] floats (+ B mel_lens tail).
    const long long row_elems = (long long)NB * ND;   // 6144
    long long total = (long long)out_size;
    int max_len;
    long long tail_elems;
    if (total % row_elems == 0) {
        max_len = (int)(total / row_elems);
        tail_elems = 0;
    } else {
        tail_elems = total % row_elems;                // typically == NB
        max_len = (int)((total - tail_elems) / row_elems);
    }

    const long long body = (long long)NB * max_len * ND;
    float* tail = out + body;

    // 1) cumsum + mel_lens
    cumsum_kernel<<<NB, NT>>>(dur, tail, tail_elems >= NB ? 1 : 0);

    // 2) expansion: 8 warps/block, one warp per output row
    const int rows = NB * max_len;
    const int warps_per_block = 8;
    const int blocks = (rows + warps_per_block - 1) / warps_per_block;
    expand_kernel<<<blocks, warps_per_block * 32>>>(enc, out, max_len);

    // 3) defensive zero of any tail elements beyond the B mel_lens slots
    if (tail_elems > NB) {
        long long rem = tail_elems - NB;
        fill_zero_kernel<<<(int)((rem + 255) / 256), 256>>>(tail + NB, rem);
    }
}

// round 2
// speedup vs baseline: 1.0664x; 1.0664x over previous
#include <cuda_runtime.h>
#include <cuda_bf16.h>

#define NB 16
#define NT 512
#define ND 384
#define MAXL 4096

// Scratch (static device globals — no runtime allocation).
__device__ int g_tok[NB * MAXL];   // token index per (b,pos), -1 => zero row

// One block per batch: inclusive scan of 512 durations in smem, then
// SCATTER the inverse map: token t owns positions [cum[t-1], cum[t]).
// Tail positions [mel, max_len) get -1. Also writes mel_lens into out tail.
__global__ void cumsum_scatter_kernel(const int* __restrict__ dur,
                                      float* __restrict__ out_tail, int has_tail,
                                      int max_len) {
    __shared__ int s[NT];
    const int b = blockIdx.x;
    const int t = threadIdx.x;
    s[t] = dur[b * NT + t];
    __syncthreads();
    #pragma unroll
    for (int off = 1; off < NT; off <<= 1) {
        int v = (t >= off) ? s[t - off] : 0;
        __syncthreads();
        s[t] += v;
        __syncthreads();
    }
    const int mel = s[NT - 1];
    if (has_tail && t == 0) out_tail[b] = (float)mel;

    int* __restrict__ tok = g_tok + b * MAXL;

    // Fill invalid tail with -1 (positions [min(mel,max_len), max_len)).
    const int start_inval = min(mel, max_len);
    for (int p = start_inval + t; p < max_len; p += NT) tok[p] = -1;

    // Scatter: this token's span (durations are small, <= ~7 iterations).
    const int lo = min((t > 0) ? s[t - 1] : 0, max_len);
    const int hi = min(s[t], max_len);
    for (int p = lo; p < hi; ++p) tok[p] = t;
}

// Pure streamed gather: one warp per 2 output rows. Each lane moves 3 float4
// per row (96 float4 = 384 floats, fully coalesced 1536B stores).
__global__ __launch_bounds__(256) void expand_kernel(const float* __restrict__ enc,
                                                     float* __restrict__ out,
                                                     int max_len, int total_rows) {
    const int w    = (blockIdx.x * blockDim.x + threadIdx.x) >> 5;
    const int lane = threadIdx.x & 31;
    const int r0   = w * 2;
    if (r0 >= total_rows) return;

    // r0 even, max_len even => r0 and r0+1 are always in the same batch.
    const int b = r0 / max_len;
    const int pos0 = r0 - b * max_len;

    // Broadcast load of both token indices in one 8B load.
    const int2 tk = *(const int2*)(g_tok + b * MAXL + pos0);
    const bool have1 = (r0 + 1 < total_rows);

    const float4 z = make_float4(0.f, 0.f, 0.f, 0.f);
    float4 v0a = z, v0b = z, v0c = z;
    float4 v1a = z, v1b = z, v1c = z;

    const float4* base = (const float4*)(enc + (size_t)b * NT * ND);
    if (tk.x >= 0) {
        const float4* s0 = base + (size_t)tk.x * (ND / 4);
        v0a = s0[lane]; v0b = s0[lane + 32]; v0c = s0[lane + 64];
    }
    if (have1 && tk.y >= 0) {
        const float4* s1 = base + (size_t)tk.y * (ND / 4);
        v1a = s1[lane]; v1b = s1[lane + 32]; v1c = s1[lane + 64];
    }

    float4* d0 = (float4*)(out + (size_t)r0 * ND);
    d0[lane] = v0a; d0[lane + 32] = v0b; d0[lane + 64] = v0c;
    if (have1) {
        float4* d1 = d0 + (ND / 4);
        d1[lane] = v1a; d1[lane + 32] = v1b; d1[lane + 64] = v1c;
    }
}

// Zero-fill any residual tail elements beyond the B mel_lens slots (defensive).
__global__ void fill_zero_kernel(float* __restrict__ p, long long n) {
    long long i = (long long)blockIdx.x * blockDim.x + threadIdx.x;
    if (i < n) p[i] = 0.f;
}

extern "C" void kernel_launch(void* const* d_in, const int* in_sizes, int n_in,
                              void* d_out, int out_size) {
    const float* enc = (const float*)d_in[0];
    const int*   dur = (const int*)d_in[1];
    float* out = (float*)d_out;

    // Derive max_len from out_size: out = [B, max_len, D] floats (+ B mel_lens tail).
    const long long row_elems = (long long)NB * ND;   // 6144
    long long total = (long long)out_size;
    int max_len;
    long long tail_elems;
    if (total % row_elems == 0) {
        max_len = (int)(total / row_elems);
        tail_elems = 0;
    } else {
        tail_elems = total % row_elems;                // typically == NB
        max_len = (int)((total - tail_elems) / row_elems);
    }
    if (max_len > MAXL) max_len = MAXL;                // static table bound

    const long long body = (long long)NB * max_len * ND;
    float* tail = out + body;

    // 1) cumsum + inverse-map scatter + mel_lens
    cumsum_scatter_kernel<<<NB, NT>>>(dur, tail, tail_elems >= NB ? 1 : 0, max_len);

    // 2) expansion: one warp per 2 rows, 8 warps/block
    const int rows = NB * max_len;
    const int warps = (rows + 1) / 2;
    const int blocks = (warps + 7) / 8;
    expand_kernel<<<blocks, 256>>>(enc, out, max_len, rows);

    // 3) defensive zero of any tail elements beyond the B mel_lens slots
    if (tail_elems > NB) {
        long long rem = tail_elems - NB;
        fill_zero_kernel<<<(int)((rem + 255) / 256), 256>>>(tail + NB, rem);
    }
}